// round 1
// baseline (speedup 1.0000x reference)
#include <cuda_runtime.h>
#include <math.h>

// Problem constants
#define BB   2
#define SS   2048
#define DD   2048
#define HH   16
#define HD   128
#define FF   8192
#define MM   (BB*SS)          // 4096 rows
#define QKVW (3*DD)           // 6144

// ---------------- scratch (device globals; no cudaMalloc allowed) ----------
__device__ float g_xn [MM*DD];        // 32 MB
__device__ float g_qkv[MM*QKVW];      // 96 MB
__device__ float g_att[MM*DD];        // 32 MB  ([B][H][S][HD] flattened == raw reshape view)
__device__ float g_h  [MM*DD];        // 32 MB
__device__ float g_a1 [MM*FF];        // 128 MB
__device__ float g_g  [MM*FF];        // 128 MB

// ---------------- RMSNorm ---------------------------------------------------
__global__ __launch_bounds__(256) void rmsnorm_kernel(
    const float* __restrict__ x, const float* __restrict__ w, float* __restrict__ out)
{
    const int row = blockIdx.x;
    const float* xr = x + row * DD;
    float ss = 0.f;
    for (int i = threadIdx.x; i < DD; i += 256) {
        float v = xr[i];
        ss = fmaf(v, v, ss);
    }
    #pragma unroll
    for (int o = 16; o; o >>= 1) ss += __shfl_xor_sync(0xffffffffu, ss, o);
    __shared__ float sred[8];
    if ((threadIdx.x & 31) == 0) sred[threadIdx.x >> 5] = ss;
    __syncthreads();
    float tot = sred[0]+sred[1]+sred[2]+sred[3]+sred[4]+sred[5]+sred[6]+sred[7];
    float sc = rsqrtf(tot * (1.0f / DD) + 1e-5f);
    float* orow = out + row * DD;
    for (int i = threadIdx.x; i < DD; i += 256)
        orow[i] = xr[i] * sc * w[i];
}

// ---------------- SGEMM NT: C = A[M,K] * B[N,K]^T (+bias, epilogues) -------
// mode 0: C = v (+bias if bias!=null)
// mode 1: C = E + relu(v + bias)
// mode 2: C = E + v + bias
__global__ __launch_bounds__(256) void sgemm_nt(
    const float* __restrict__ A, const float* __restrict__ Bm,
    const float* __restrict__ bias, const float* __restrict__ E,
    float* __restrict__ C, int M, int N, int K, int mode)
{
    __shared__ float As[16][132];
    __shared__ float Bs[16][132];

    const int tid = threadIdx.x;
    const int tx  = tid & 15;
    const int ty  = tid >> 4;
    const int m0  = blockIdx.y * 128;
    const int n0  = blockIdx.x * 128;

    float acc[8][8];
    #pragma unroll
    for (int i = 0; i < 8; i++)
        #pragma unroll
        for (int j = 0; j < 8; j++) acc[i][j] = 0.f;

    const int lrow = tid >> 2;        // 0..63
    const int lk   = (tid & 3) * 4;   // 0,4,8,12

    const float* Aptr = A  + (m0 + lrow) * K + lk;
    const float* Bptr = Bm + (n0 + lrow) * K + lk;

    for (int k0 = 0; k0 < K; k0 += 16) {
        float4 a0 = *(const float4*)(Aptr + k0);
        float4 a1 = *(const float4*)(Aptr + 64 * K + k0);
        float4 b0 = *(const float4*)(Bptr + k0);
        float4 b1 = *(const float4*)(Bptr + 64 * K + k0);

        As[lk+0][lrow]    = a0.x; As[lk+1][lrow]    = a0.y;
        As[lk+2][lrow]    = a0.z; As[lk+3][lrow]    = a0.w;
        As[lk+0][64+lrow] = a1.x; As[lk+1][64+lrow] = a1.y;
        As[lk+2][64+lrow] = a1.z; As[lk+3][64+lrow] = a1.w;

        Bs[lk+0][lrow]    = b0.x; Bs[lk+1][lrow]    = b0.y;
        Bs[lk+2][lrow]    = b0.z; Bs[lk+3][lrow]    = b0.w;
        Bs[lk+0][64+lrow] = b1.x; Bs[lk+1][64+lrow] = b1.y;
        Bs[lk+2][64+lrow] = b1.z; Bs[lk+3][64+lrow] = b1.w;

        __syncthreads();

        #pragma unroll
        for (int kk = 0; kk < 16; kk++) {
            float a[8], b[8];
            *(float4*)(a)     = *(const float4*)&As[kk][ty*4];
            *(float4*)(a + 4) = *(const float4*)&As[kk][64 + ty*4];
            *(float4*)(b)     = *(const float4*)&Bs[kk][tx*4];
            *(float4*)(b + 4) = *(const float4*)&Bs[kk][64 + tx*4];
            #pragma unroll
            for (int i = 0; i < 8; i++)
                #pragma unroll
                for (int j = 0; j < 8; j++)
                    acc[i][j] = fmaf(a[i], b[j], acc[i][j]);
        }
        __syncthreads();
    }

    // epilogue
    #pragma unroll
    for (int ih = 0; ih < 2; ih++)
    #pragma unroll
    for (int i = 0; i < 4; i++) {
        const int m = m0 + ih*64 + ty*4 + i;
        #pragma unroll
        for (int jh = 0; jh < 2; jh++) {
            const int n   = n0 + jh*64 + tx*4;
            const int idx = m * N + n;
            float v[4];
            #pragma unroll
            for (int j = 0; j < 4; j++) {
                v[j] = acc[ih*4 + i][jh*4 + j];
                if (bias) v[j] += bias[n + j];
            }
            if (mode == 1) {
                #pragma unroll
                for (int j = 0; j < 4; j++) v[j] = E[idx + j] + fmaxf(v[j], 0.f);
            } else if (mode == 2) {
                #pragma unroll
                for (int j = 0; j < 4; j++) v[j] = E[idx + j] + v[j];
            }
            float4 o = make_float4(v[0], v[1], v[2], v[3]);
            *(float4*)(C + idx) = o;
        }
    }
}

// ---------------- causal flash attention (fp32) -----------------------------
// qkv layout: [M = B*S rows][6144 cols]; col = (qkvIdx*H + h)*128 + d
// out layout: [B][H][S][HD] flattened (raw-reshape view, matches reference)
#define BR 64
#define BC 64
__global__ __launch_bounds__(256) void attn_kernel(
    const float* __restrict__ qkv, float* __restrict__ out)
{
    extern __shared__ float smdyn[];
    float* Ks = smdyn;                  // 64 x 132
    float* Vs = smdyn + 64*132;        // 64 x 132
    float* Sb = smdyn + 2*64*132;      // 64 x 68

    const int tid = threadIdx.x;
    const int qt  = blockIdx.x;
    const int hh  = blockIdx.y;
    const int bb  = blockIdx.z;
    const int q0  = qt * BR;

    const int r  = tid >> 2;   // 0..63 local q row
    const int g  = tid & 3;    // dim-group
    const int qi = q0 + r;

    // Q row slice in registers: chunks (g + 4*dd), dd=0..7  -> 32 floats
    float4 qreg[8];
    {
        const float* qp = qkv + (bb*SS + qi) * QKVW + hh * HD;
        #pragma unroll
        for (int dd = 0; dd < 8; dd++)
            qreg[dd] = *(const float4*)(qp + (g + 4*dd) * 4);
    }

    float m = -INFINITY, l = 0.f;
    float4 acc[8];
    #pragma unroll
    for (int dd = 0; dd < 8; dd++) acc[dd] = make_float4(0.f, 0.f, 0.f, 0.f);

    const int njt = q0 / BC + 1;
    for (int jt = 0; jt < njt; jt++) {
        const int j0 = jt * BC;
        __syncthreads();   // prev tile's consumers done before K/V overwrite
        #pragma unroll
        for (int li = 0; li < 8; li++) {
            int id  = tid + li * 256;
            int rr  = id >> 5;
            int d4  = (id & 31) * 4;
            int gro = (bb*SS + j0 + rr) * QKVW + hh * HD + d4;
            *(float4*)&Ks[rr*132 + d4] = *(const float4*)(qkv + gro + HH*HD);
            *(float4*)&Vs[rr*132 + d4] = *(const float4*)(qkv + gro + 2*HH*HD);
        }
        __syncthreads();

        // scores: each thread computes partial dot over its 32 dims for all c,
        // reduced over the 4 lanes of the row-group via shfl.
        #pragma unroll 4
        for (int c = 0; c < BC; c++) {
            const float4* kp = (const float4*)&Ks[c*132];
            float s = 0.f;
            #pragma unroll
            for (int dd = 0; dd < 8; dd++) {
                float4 kv = kp[g + 4*dd];
                s = fmaf(qreg[dd].x, kv.x, s);
                s = fmaf(qreg[dd].y, kv.y, s);
                s = fmaf(qreg[dd].z, kv.z, s);
                s = fmaf(qreg[dd].w, kv.w, s);
            }
            s += __shfl_xor_sync(0xffffffffu, s, 1);
            s += __shfl_xor_sync(0xffffffffu, s, 2);
            if (g == 0) {
                s *= 0.08838834764831845f;       // 1/sqrt(128)
                if (j0 + c > qi) s = -INFINITY;  // causal mask
                Sb[r*68 + c] = s;
            }
        }
        __syncwarp();  // Sb row r is produced/consumed within one warp

        // online softmax update
        float mNew = m;
        #pragma unroll 8
        for (int c = 0; c < BC; c++) mNew = fmaxf(mNew, Sb[r*68 + c]);
        float corr = __expf(m - mNew);   // m=-inf first iter -> corr=0 (mNew finite)
        m = mNew;
        l *= corr;
        #pragma unroll
        for (int dd = 0; dd < 8; dd++) {
            acc[dd].x *= corr; acc[dd].y *= corr;
            acc[dd].z *= corr; acc[dd].w *= corr;
        }
        #pragma unroll 2
        for (int c = 0; c < BC; c++) {
            float p = __expf(Sb[r*68 + c] - mNew);
            l += p;
            const float4* vp = (const float4*)&Vs[c*132];
            #pragma unroll
            for (int dd = 0; dd < 8; dd++) {
                float4 vv = vp[g + 4*dd];
                acc[dd].x = fmaf(p, vv.x, acc[dd].x);
                acc[dd].y = fmaf(p, vv.y, acc[dd].y);
                acc[dd].z = fmaf(p, vv.z, acc[dd].z);
                acc[dd].w = fmaf(p, vv.w, acc[dd].w);
            }
        }
    }

    const float inv = 1.f / l;
    const int obase = ((bb*HH + hh)*SS + qi) * HD;
    #pragma unroll
    for (int dd = 0; dd < 8; dd++) {
        float4 o = acc[dd];
        o.x *= inv; o.y *= inv; o.z *= inv; o.w *= inv;
        *(float4*)(out + obase + (g + 4*dd) * 4) = o;
    }
}

// ---------------- launch -----------------------------------------------------
extern "C" void kernel_launch(void* const* d_in, const int* in_sizes, int n_in,
                              void* d_out, int out_size)
{
    (void)in_sizes; (void)n_in; (void)out_size;
    const float* x     = (const float*)d_in[0];
    const float* rms_w = (const float*)d_in[1];
    const float* w_qkv = (const float*)d_in[2];
    const float* w_out = (const float*)d_in[3];
    const float* w1    = (const float*)d_in[4];
    const float* b1    = (const float*)d_in[5];
    const float* w3    = (const float*)d_in[6];
    const float* b3    = (const float*)d_in[7];
    const float* w2    = (const float*)d_in[8];
    const float* b2    = (const float*)d_in[9];
    float* out = (float*)d_out;

    float *xn, *qkv, *att, *h, *a1, *gg;
    cudaGetSymbolAddress((void**)&xn,  g_xn);
    cudaGetSymbolAddress((void**)&qkv, g_qkv);
    cudaGetSymbolAddress((void**)&att, g_att);
    cudaGetSymbolAddress((void**)&h,   g_h);
    cudaGetSymbolAddress((void**)&a1,  g_a1);
    cudaGetSymbolAddress((void**)&gg,  g_g);

    const int attn_smem = (2*64*132 + 64*68) * (int)sizeof(float);  // ~84 KB
    cudaFuncSetAttribute(attn_kernel, cudaFuncAttributeMaxDynamicSharedMemorySize, attn_smem);

    // 1) RMSNorm
    rmsnorm_kernel<<<MM, 256>>>(x, rms_w, xn);

    // 2) QKV projection: [4096,2048] @ [6144,2048]^T
    sgemm_nt<<<dim3(QKVW/128, MM/128), 256>>>(xn, w_qkv, nullptr, nullptr, qkv,
                                              MM, QKVW, DD, 0);

    // 3) causal attention
    attn_kernel<<<dim3(SS/BR, HH, BB), 256, attn_smem>>>(qkv, att);

    // 4) out projection (att viewed as [4096,2048], raw-reshape semantics)
    sgemm_nt<<<dim3(DD/128, MM/128), 256>>>(att, w_out, nullptr, nullptr, h,
                                            MM, DD, DD, 0);

    // 5) a1 = h @ w1^T + b1
    sgemm_nt<<<dim3(FF/128, MM/128), 256>>>(h, w1, b1, nullptr, a1,
                                            MM, FF, DD, 0);

    // 6) g = a1 + relu(h @ w3^T + b3)
    sgemm_nt<<<dim3(FF/128, MM/128), 256>>>(h, w3, b3, a1, gg,
                                            MM, FF, DD, 1);

    // 7) out = x + g @ w2^T + b2
    sgemm_nt<<<dim3(DD/128, MM/128), 256>>>(gg, w2, b2, x, out,
                                            MM, DD, FF, 2);
}

// round 3
// speedup vs baseline: 2.2332x; 2.2332x over previous
#include <cuda_runtime.h>
#include <cuda_bf16.h>
#include <math.h>
#include <stdint.h>

#define BB   2
#define SS   2048
#define DD   2048
#define HH   16
#define HD   128
#define FF   8192
#define MM   (BB*SS)          // 4096
#define QKVW (3*DD)           // 6144

// ---------------- fp32 scratch ----------------
__device__ float g_xn [MM*DD];
__device__ float g_qkv[MM*QKVW];
__device__ float g_att[MM*DD];
__device__ float g_h  [MM*DD];
__device__ float g_a1 [MM*FF];
__device__ float g_g  [MM*FF];

// ---------------- bf16 split scratch (tile-packed [rows/128][3K/64][128][64], SW128 swizzled)
__device__ __nv_bfloat16 g_xn3 [(size_t)MM*3*DD];
__device__ __nv_bfloat16 g_att3[(size_t)MM*3*DD];
__device__ __nv_bfloat16 g_h3  [(size_t)MM*3*DD];
__device__ __nv_bfloat16 g_gg3 [(size_t)MM*3*FF];
__device__ __nv_bfloat16 g_wqkv3[(size_t)QKVW*3*DD];
__device__ __nv_bfloat16 g_wout3[(size_t)DD*3*DD];
__device__ __nv_bfloat16 g_w13 [(size_t)FF*3*DD];
__device__ __nv_bfloat16 g_w33 [(size_t)FF*3*DD];
__device__ __nv_bfloat16 g_w23 [(size_t)DD*3*FF];

// ---------------- PTX helpers (sm_90 baseline features only) -----------------
__device__ __forceinline__ uint32_t smem_u32(const void* p) {
    uint32_t a;
    asm("{ .reg .u64 t; cvta.to.shared.u64 t, %1; cvt.u32.u64 %0, t; }" : "=r"(a) : "l"(p));
    return a;
}
__device__ __forceinline__ uint32_t elect_one() {
    uint32_t p;
    asm volatile("{ .reg .pred p; elect.sync _|p, 0xFFFFFFFF; selp.b32 %0,1,0,p; }" : "=r"(p));
    return p;
}
#define MBAR_INIT(a, c) \
    asm volatile("mbarrier.init.shared.b64 [%0], %1;" :: "r"(a), "r"(c) : "memory")
#define MBAR_EXPECT(a, b) \
    asm volatile("mbarrier.arrive.expect_tx.shared.b64 _, [%0], %1;" :: "r"(a), "r"(b) : "memory")
#define MBAR_ARRIVE(a) \
    asm volatile("mbarrier.arrive.shared.b64 _, [%0];" :: "r"(a) : "memory")
#define MBAR_WAIT(a, ph) do { uint32_t _m=(a), _p=(ph), _d;                                   \
    asm volatile("{ .reg .pred p; mbarrier.try_wait.parity.acquire.cta.shared::cta.b64 p, [%1], %2; selp.b32 %0,1,0,p; }" \
                 : "=r"(_d) : "r"(_m), "r"(_p) : "memory");                                   \
    if (!_d) {                                                                                \
      asm volatile("{ .reg .pred P1; WL%=: mbarrier.try_wait.parity.acquire.cta.shared::cta.b64 P1, [%0], %1, 0x989680; @P1 bra.uni WD%=; bra.uni WL%=; WD%=: }" \
                   :: "r"(_m), "r"(_p) : "memory"); } } while(0)
#define BULK_G2S(d, s, n, m) \
    asm volatile("cp.async.bulk.shared::cta.global.mbarrier::complete_tx::bytes [%0], [%1], %2, [%3];" \
                 :: "r"(d), "l"(s), "r"(n), "r"(m) : "memory")
#define LDSM_X4(r0, r1, r2, r3, a) \
    asm volatile("ldmatrix.sync.aligned.m8n8.x4.shared.b16 {%0,%1,%2,%3}, [%4];" \
                 : "=r"(r0), "=r"(r1), "=r"(r2), "=r"(r3) : "r"(a))
#define MMA16816(d, av, bv) \
    asm volatile("mma.sync.aligned.m16n8k16.row.col.f32.bf16.bf16.f32 " \
                 "{%0,%1,%2,%3}, {%4,%5,%6,%7}, {%8,%9}, {%0,%1,%2,%3};" \
                 : "+f"((d)[0]), "+f"((d)[1]), "+f"((d)[2]), "+f"((d)[3]) \
                 : "r"((av)[0]), "r"((av)[1]), "r"((av)[2]), "r"((av)[3]), \
                   "r"((bv)[0]), "r"((bv)[1]))

// ---------------- RMSNorm ----------------------------------------------------
__global__ __launch_bounds__(256) void rmsnorm_kernel(
    const float* __restrict__ x, const float* __restrict__ w, float* __restrict__ out)
{
    const int row = blockIdx.x;
    const float* xr = x + (size_t)row * DD;
    float ss = 0.f;
    for (int i = threadIdx.x; i < DD; i += 256) { float v = xr[i]; ss = fmaf(v, v, ss); }
    #pragma unroll
    for (int o = 16; o; o >>= 1) ss += __shfl_xor_sync(0xffffffffu, ss, o);
    __shared__ float sred[8];
    if ((threadIdx.x & 31) == 0) sred[threadIdx.x >> 5] = ss;
    __syncthreads();
    float tot = sred[0]+sred[1]+sred[2]+sred[3]+sred[4]+sred[5]+sred[6]+sred[7];
    float sc = rsqrtf(tot * (1.0f / DD) + 1e-5f);
    float* orow = out + (size_t)row * DD;
    for (int i = threadIdx.x; i < DD; i += 256) orow[i] = xr[i] * sc * w[i];
}

// ---------------- fp32 -> bf16 hi/lo split, tile-packed, pre-swizzled --------
// acts:    copies along K' are (hi, lo, hi)
// weights: copies along K' are (hi, hi, lo)
// so term-by-term: hi*hi + lo*hi + hi*lo
__global__ __launch_bounds__(256) void convert3(
    const float* __restrict__ src, __nv_bfloat16* __restrict__ dst,
    int K, int is_weight, int total4)
{
    int gid = blockIdx.x * 256 + threadIdx.x;
    if (gid >= total4) return;
    const int kq = K >> 2;
    const int m  = gid / kq;
    const int k  = (gid - m * kq) << 2;

    float4 v = *(const float4*)(src + (size_t)m * K + k);
    float vv[4] = {v.x, v.y, v.z, v.w};
    unsigned short hib[4], lob[4];
    #pragma unroll
    for (int i = 0; i < 4; i++) {
        __nv_bfloat16 h = __float2bfloat16(vv[i]);
        __nv_bfloat16 l = __float2bfloat16(vv[i] - __bfloat162float(h));
        hib[i] = __bfloat16_as_ushort(h);
        lob[i] = __bfloat16_as_ushort(l);
    }
    uint2 hp = make_uint2((uint32_t)hib[0] | ((uint32_t)hib[1] << 16),
                          (uint32_t)hib[2] | ((uint32_t)hib[3] << 16));
    uint2 lp = make_uint2((uint32_t)lob[0] | ((uint32_t)lob[1] << 16),
                          (uint32_t)lob[2] | ((uint32_t)lob[3] << 16));

    const int ktiles = (3 * K) >> 6;
    const int mt = m >> 7, mr = m & 127;       // row tile = 128
    char* db = (char*)dst;

    #pragma unroll
    for (int copy = 0; copy < 3; copy++) {
        uint2 pk = (copy == 0) ? hp
                 : (copy == 1) ? (is_weight ? hp : lp)
                                : (is_weight ? lp : hp);
        int kk = k + copy * K;
        int kt = kk >> 6, c = kk & 63;
        size_t base = ((size_t)mt * ktiles + kt) * 16384;
        uint32_t off = (uint32_t)(mr * 128 + c * 2);
        off = off ^ ((off >> 3) & 0x70);
        *(uint2*)(db + base + off) = pk;
    }
}

// ---------------- bf16 mma.sync GEMM: C[M,N] = A'[M,K3] * B'[N,K3]^T ---------
// 128x128 CTA tile, 8 compute warps (32x64 each) + 1 producer warp.
// mode 0: C = v (+bias) ; mode 1: C = E + relu(v+bias) ; mode 2: C = E + v + bias
#define G_STG    4
#define G_TB     16384                         // 128x64 bf16 tile bytes
#define G_SMEM   (1024 + G_STG*2*G_TB)         // 132096

__global__ __launch_bounds__(288, 1) void gemm_mma(
    const __nv_bfloat16* __restrict__ A3, const __nv_bfloat16* __restrict__ B3,
    const float* __restrict__ bias, const float* __restrict__ E,
    float* __restrict__ C, int N, int K3, int mode)
{
    extern __shared__ char sm[];
    const uint32_t sb = smem_u32(sm);
    const int tid = threadIdx.x, wid = tid >> 5, lane = tid & 31;

    const uint32_t MFULL  = sb;            // G_STG x 8B
    const uint32_t MEMPTY = sb + 256;      // G_STG x 8B
    const uint32_t SA     = sb + 1024;
    const uint32_t SBq    = SA + G_STG * G_TB;

    if (tid == 0) {
        #pragma unroll
        for (int s = 0; s < G_STG; s++) { MBAR_INIT(MFULL + s*8, 1); MBAR_INIT(MEMPTY + s*8, 8); }
    }
    __syncthreads();

    const int ktiles = K3 >> 6;
    const int nt = blockIdx.x, mt = blockIdx.y;

    float d[2][8][4];
    #pragma unroll
    for (int a = 0; a < 2; a++)
        #pragma unroll
        for (int b = 0; b < 8; b++)
            #pragma unroll
            for (int c = 0; c < 4; c++) d[a][b][c] = 0.f;

    if (wid == 8) {
        // ---- producer ----
        if (elect_one()) {
            const char* Ag = (const char*)A3 + (size_t)mt * ktiles * G_TB;
            const char* Bg = (const char*)B3 + (size_t)nt * ktiles * G_TB;
            int s = 0, ph = 1;
            for (int kt = 0; kt < ktiles; kt++) {
                MBAR_WAIT(MEMPTY + s*8, ph);
                MBAR_EXPECT(MFULL + s*8, 2*G_TB);
                BULK_G2S(SA  + s*G_TB, Ag + (size_t)kt*G_TB, G_TB, MFULL + s*8);
                BULK_G2S(SBq + s*G_TB, Bg + (size_t)kt*G_TB, G_TB, MFULL + s*8);
                if (++s == G_STG) { s = 0; ph ^= 1; }
            }
        }
    } else {
        // ---- consumers: warp tile 32(M) x 64(N) ----
        const int wm = (wid & 3) * 32;
        const int wn = (wid >> 2) * 64;
        // ldmatrix lane addressing (A and B share the same pattern)
        const uint32_t rsub   = (uint32_t)(((lane >> 3) & 1) * 8 + (lane & 7));
        const uint32_t ksel   = (uint32_t)((lane >> 4) * 16);    // byte offset (8 elems)
        const uint32_t cmask  = (uint32_t)((lane & 7) << 4);     // SW128 xor key
        const uint32_t aRowOff = (uint32_t)(wm + rsub) * 128;
        const uint32_t bRowOff = (uint32_t)(wn + rsub) * 128;

        int s = 0, ph = 0;
        for (int kt = 0; kt < ktiles; kt++) {
            MBAR_WAIT(MFULL + s*8, ph);
            const uint32_t sa  = SA  + s*G_TB;
            const uint32_t sbb = SBq + s*G_TB;
            #pragma unroll
            for (int kk4 = 0; kk4 < 4; kk4++) {
                const uint32_t ko = (uint32_t)(kk4*32 + ksel) ^ cmask;
                uint32_t af[2][4];
                #pragma unroll
                for (int mi = 0; mi < 2; mi++)
                    LDSM_X4(af[mi][0], af[mi][1], af[mi][2], af[mi][3],
                            sa + aRowOff + mi*2048 + ko);
                uint32_t bf[8][2];
                #pragma unroll
                for (int ng = 0; ng < 4; ng++) {
                    uint32_t t0, t1, t2, t3;
                    LDSM_X4(t0, t1, t2, t3, sbb + bRowOff + ng*2048 + ko);
                    bf[2*ng][0] = t0; bf[2*ng+1][0] = t1;
                    bf[2*ng][1] = t2; bf[2*ng+1][1] = t3;
                }
                #pragma unroll
                for (int mi = 0; mi < 2; mi++)
                    #pragma unroll
                    for (int ni = 0; ni < 8; ni++)
                        MMA16816(d[mi][ni], af[mi], bf[ni]);
            }
            if (lane == 0) MBAR_ARRIVE(MEMPTY + s*8);
            if (++s == G_STG) { s = 0; ph ^= 1; }
        }
    }

    __syncthreads();

    // ---- epilogue: regs -> smem staging -> coalesced fused store ----
    float* st = (float*)(sm + 1024);     // 128 x 132 floats
    if (wid < 8) {
        const int wm = (wid & 3) * 32;
        const int wn = (wid >> 2) * 64;
        const int r0 = lane >> 2;
        const int cc = (lane & 3) * 2;
        #pragma unroll
        for (int mi = 0; mi < 2; mi++)
            #pragma unroll
            for (int ni = 0; ni < 8; ni++) {
                const int r = wm + mi*16 + r0;
                const int c = wn + ni*8 + cc;
                st[r*132 + c]       = d[mi][ni][0];
                st[r*132 + c + 1]   = d[mi][ni][1];
                st[(r+8)*132 + c]   = d[mi][ni][2];
                st[(r+8)*132 + c+1] = d[mi][ni][3];
            }
    }
    __syncthreads();

    if (tid < 256) {
        const int r0 = tid >> 5;
        const int c  = (tid & 31) * 4;
        const int n  = nt*128 + c;
        float4 bv = make_float4(0.f, 0.f, 0.f, 0.f);
        if (bias) bv = *(const float4*)(bias + n);
        #pragma unroll 4
        for (int rp = 0; rp < 16; rp++) {
            const int r = rp*8 + r0;
            const size_t idx = (size_t)(mt*128 + r) * N + n;
            float4 v = *(float4*)&st[r*132 + c];
            v.x += bv.x; v.y += bv.y; v.z += bv.z; v.w += bv.w;
            if (mode == 1) {
                float4 e = *(const float4*)(E + idx);
                v.x = e.x + fmaxf(v.x, 0.f); v.y = e.y + fmaxf(v.y, 0.f);
                v.z = e.z + fmaxf(v.z, 0.f); v.w = e.w + fmaxf(v.w, 0.f);
            } else if (mode == 2) {
                float4 e = *(const float4*)(E + idx);
                v.x += e.x; v.y += e.y; v.z += e.z; v.w += e.w;
            }
            *(float4*)(C + idx) = v;
        }
    }
}

// ---------------- causal flash attention (fp32) ------------------------------
#define BR 64
#define BC 64
__global__ __launch_bounds__(256) void attn_kernel(
    const float* __restrict__ qkv, float* __restrict__ out)
{
    extern __shared__ float smdyn[];
    float* Ks = smdyn;
    float* Vs = smdyn + 64*132;
    float* Sb = smdyn + 2*64*132;

    const int tid = threadIdx.x;
    const int qt  = blockIdx.x;
    const int hh  = blockIdx.y;
    const int bb  = blockIdx.z;
    const int q0  = qt * BR;

    const int r  = tid >> 2;
    const int g  = tid & 3;
    const int qi = q0 + r;

    float4 qreg[8];
    {
        const float* qp = qkv + (size_t)(bb*SS + qi) * QKVW + hh * HD;
        #pragma unroll
        for (int dd = 0; dd < 8; dd++) qreg[dd] = *(const float4*)(qp + (g + 4*dd) * 4);
    }

    float m = -INFINITY, l = 0.f;
    float4 acc[8];
    #pragma unroll
    for (int dd = 0; dd < 8; dd++) acc[dd] = make_float4(0.f,0.f,0.f,0.f);

    const int njt = q0 / BC + 1;
    for (int jt = 0; jt < njt; jt++) {
        const int j0 = jt * BC;
        __syncthreads();
        #pragma unroll
        for (int li = 0; li < 8; li++) {
            int id  = tid + li * 256;
            int rr  = id >> 5;
            int d4  = (id & 31) * 4;
            size_t gro = (size_t)(bb*SS + j0 + rr) * QKVW + hh * HD + d4;
            *(float4*)&Ks[rr*132 + d4] = *(const float4*)(qkv + gro + HH*HD);
            *(float4*)&Vs[rr*132 + d4] = *(const float4*)(qkv + gro + 2*HH*HD);
        }
        __syncthreads();

        #pragma unroll 4
        for (int c = 0; c < BC; c++) {
            const float4* kp = (const float4*)&Ks[c*132];
            float s = 0.f;
            #pragma unroll
            for (int dd = 0; dd < 8; dd++) {
                float4 kv = kp[g + 4*dd];
                s = fmaf(qreg[dd].x, kv.x, s); s = fmaf(qreg[dd].y, kv.y, s);
                s = fmaf(qreg[dd].z, kv.z, s); s = fmaf(qreg[dd].w, kv.w, s);
            }
            s += __shfl_xor_sync(0xffffffffu, s, 1);
            s += __shfl_xor_sync(0xffffffffu, s, 2);
            if (g == 0) {
                s *= 0.08838834764831845f;
                if (j0 + c > qi) s = -INFINITY;
                Sb[r*68 + c] = s;
            }
        }
        __syncwarp();

        float mNew = m;
        #pragma unroll 8
        for (int c = 0; c < BC; c++) mNew = fmaxf(mNew, Sb[r*68 + c]);
        float corr = __expf(m - mNew);
        m = mNew; l *= corr;
        #pragma unroll
        for (int dd = 0; dd < 8; dd++) {
            acc[dd].x *= corr; acc[dd].y *= corr; acc[dd].z *= corr; acc[dd].w *= corr;
        }
        #pragma unroll 2
        for (int c = 0; c < BC; c++) {
            float p = __expf(Sb[r*68 + c] - mNew);
            l += p;
            const float4* vp = (const float4*)&Vs[c*132];
            #pragma unroll
            for (int dd = 0; dd < 8; dd++) {
                float4 vv = vp[g + 4*dd];
                acc[dd].x = fmaf(p, vv.x, acc[dd].x); acc[dd].y = fmaf(p, vv.y, acc[dd].y);
                acc[dd].z = fmaf(p, vv.z, acc[dd].z); acc[dd].w = fmaf(p, vv.w, acc[dd].w);
            }
        }
    }

    const float inv = 1.f / l;
    const size_t obase = (size_t)((bb*HH + hh)*SS + qi) * HD;
    #pragma unroll
    for (int dd = 0; dd < 8; dd++) {
        float4 o = acc[dd];
        o.x *= inv; o.y *= inv; o.z *= inv; o.w *= inv;
        *(float4*)(out + obase + (g + 4*dd) * 4) = o;
    }
}

// ---------------- launch ------------------------------------------------------
static inline void conv(const float* s, __nv_bfloat16* d, int rows, int K, int isw) {
    int total4 = rows * (K >> 2);
    convert3<<<(total4 + 255) / 256, 256>>>(s, d, K, isw, total4);
}

extern "C" void kernel_launch(void* const* d_in, const int* in_sizes, int n_in,
                              void* d_out, int out_size)
{
    (void)in_sizes; (void)n_in; (void)out_size;
    const float* x     = (const float*)d_in[0];
    const float* rms_w = (const float*)d_in[1];
    const float* w_qkv = (const float*)d_in[2];
    const float* w_out = (const float*)d_in[3];
    const float* w1    = (const float*)d_in[4];
    const float* b1    = (const float*)d_in[5];
    const float* w3    = (const float*)d_in[6];
    const float* b3    = (const float*)d_in[7];
    const float* w2    = (const float*)d_in[8];
    const float* b2    = (const float*)d_in[9];
    float* out = (float*)d_out;

    float *xn,*qkv,*att,*h,*a1,*gg;
    cudaGetSymbolAddress((void**)&xn,  g_xn);
    cudaGetSymbolAddress((void**)&qkv, g_qkv);
    cudaGetSymbolAddress((void**)&att, g_att);
    cudaGetSymbolAddress((void**)&h,   g_h);
    cudaGetSymbolAddress((void**)&a1,  g_a1);
    cudaGetSymbolAddress((void**)&gg,  g_g);
    __nv_bfloat16 *xn3,*att3,*h3,*gg3,*wqkv3,*wout3,*w13,*w33,*w23;
    cudaGetSymbolAddress((void**)&xn3,   g_xn3);
    cudaGetSymbolAddress((void**)&att3,  g_att3);
    cudaGetSymbolAddress((void**)&h3,    g_h3);
    cudaGetSymbolAddress((void**)&gg3,   g_gg3);
    cudaGetSymbolAddress((void**)&wqkv3, g_wqkv3);
    cudaGetSymbolAddress((void**)&wout3, g_wout3);
    cudaGetSymbolAddress((void**)&w13,   g_w13);
    cudaGetSymbolAddress((void**)&w33,   g_w33);
    cudaGetSymbolAddress((void**)&w23,   g_w23);

    cudaFuncSetAttribute(gemm_mma, cudaFuncAttributeMaxDynamicSharedMemorySize, G_SMEM);
    const int attn_smem = (2*64*132 + 64*68) * (int)sizeof(float);
    cudaFuncSetAttribute(attn_kernel, cudaFuncAttributeMaxDynamicSharedMemorySize, attn_smem);

    // weight conversions (independent of activations)
    conv(w_qkv, wqkv3, QKVW, DD, 1);
    conv(w_out, wout3, DD,   DD, 1);
    conv(w1,    w13,   FF,   DD, 1);
    conv(w3,    w33,   FF,   DD, 1);
    conv(w2,    w23,   DD,   FF, 1);

    // 1) RMSNorm + convert
    rmsnorm_kernel<<<MM, 256>>>(x, rms_w, xn);
    conv(xn, xn3, MM, DD, 0);

    // 2) QKV projection
    gemm_mma<<<dim3(QKVW/128, MM/128), 288, G_SMEM>>>(xn3, wqkv3, nullptr, nullptr, qkv, QKVW, 3*DD, 0);

    // 3) attention
    attn_kernel<<<dim3(SS/BR, HH, BB), 256, attn_smem>>>(qkv, att);
    conv(att, att3, MM, DD, 0);

    // 4) out projection
    gemm_mma<<<dim3(DD/128, MM/128), 288, G_SMEM>>>(att3, wout3, nullptr, nullptr, h, DD, 3*DD, 0);
    conv(h, h3, MM, DD, 0);

    // 5) a1 = h @ w1^T + b1
    gemm_mma<<<dim3(FF/128, MM/128), 288, G_SMEM>>>(h3, w13, b1, nullptr, a1, FF, 3*DD, 0);

    // 6) g = a1 + relu(h @ w3^T + b3)
    gemm_mma<<<dim3(FF/128, MM/128), 288, G_SMEM>>>(h3, w33, b3, a1, gg, FF, 3*DD, 1);
    conv(gg, gg3, MM, FF, 0);

    // 7) out = x + g @ w2^T + b2
    gemm_mma<<<dim3(DD/128, MM/128), 288, G_SMEM>>>(gg3, w23, b2, x, out, DD, 3*FF, 2);
}